// round 1
// baseline (speedup 1.0000x reference)
#include <cuda_runtime.h>

#define CIN   6
#define COUT  16
#define FS    5
#define HIN   512
#define WIN   512
#define HOUT  508
#define WOUT  508
#define BATCHN 32

// Dense [ky][kx][ci][co] kernel with structural zeros, built per launch.
__device__ float g_Wd[FS * FS * CIN * COUT];

__global__ void build_weights(const float* __restrict__ w3,
                              const float* __restrict__ w4,
                              const float* __restrict__ w44,
                              const float* __restrict__ w6) {
    int idx = blockIdx.x * blockDim.x + threadIdx.x;
    if (idx >= FS * FS * CIN * COUT) return;
    int co = idx % COUT;
    int ci = (idx / COUT) % CIN;
    int kk = idx / (COUT * CIN);   // ky*5 + kx
    float v = 0.f;
    if (co < 6) {
        int i = co;
        #pragma unroll
        for (int m = 0; m < 3; ++m)
            if (ci == (i + m) % 6) v = w3[(kk * 3 + m) * 6 + i];
    } else if (co < 12) {
        int k = co - 6;
        #pragma unroll
        for (int m = 0; m < 4; ++m)
            if (ci == (k + m) % 6) v = w4[(kk * 4 + m) * 6 + k];
    } else if (co < 15) {
        int k = co - 12;
        const int off[4] = {0, 1, 3, 4};
        #pragma unroll
        for (int m = 0; m < 4; ++m)
            if (ci == (k + off[m]) % 6) v = w44[(kk * 4 + m) * 3 + k];
    } else {
        v = w6[kk * 6 + ci];
    }
    g_Wd[idx] = v;
}

// ---- packed f32x2 helpers (Blackwell FFMA2 only reachable via PTX) ----
__device__ __forceinline__ unsigned long long pack2(float lo, float hi) {
    unsigned long long r;
    asm("mov.b64 %0, {%1, %2};" : "=l"(r) : "f"(lo), "f"(hi));
    return r;
}
__device__ __forceinline__ void ffma2(unsigned long long& acc,
                                      unsigned long long a,
                                      unsigned long long b) {
    asm("fma.rn.f32x2 %0, %1, %2, %0;" : "+l"(acc) : "l"(a), "l"(b));
}

// Tile: 16 rows x 64 cols of output per 256-thread block.
// Each thread: 4 consecutive rows x 1 col x 16 couts = 32 f32x2 accumulators.
#define TH 16
#define TW 64
#define IH (TH + 4)   // 20
#define IW (TW + 4)   // 68

__global__ __launch_bounds__(256) void conv_dense_kernel(
    const float* __restrict__ in,
    const float* __restrict__ bias,
    float* __restrict__ out) {

    __shared__ float s_in[CIN][IH][IW];                 // 32640 B, [ci] planes -> conflict-free LDS
    __shared__ __align__(16) float s_w[FS * FS * CIN][COUT];  // 9600 B, co contiguous -> LDS.64 broadcast
    __shared__ float s_bias[COUT];

    const int tid = threadIdx.x;
    const int b  = blockIdx.z;
    const int y0 = blockIdx.y * TH;
    const int x0 = blockIdx.x * TW;

    // Stage weights + bias
    for (int i = tid; i < FS * FS * CIN * COUT; i += 256)
        ((float*)s_w)[i] = g_Wd[i];
    if (tid < COUT) s_bias[tid] = bias[tid];

    // Stage input tile: iterate in global-contiguous order (coalesced LDG),
    // scatter into [ci][row][col] smem layout.
    const float* inb = in + (long long)b * (HIN * WIN * CIN);
    for (int idx = tid; idx < IH * IW * CIN; idx += 256) {
        int r  = idx / (IW * CIN);
        int t  = idx - r * (IW * CIN);
        int c  = t / CIN;
        int ci = t - c * CIN;
        int gy = y0 + r, gx = x0 + c;
        float v = 0.f;
        if (gy < HIN && gx < WIN)
            v = inb[(gy * WIN + gx) * CIN + ci];
        s_in[ci][r][c] = v;
    }
    __syncthreads();

    const int tx = tid & 63;        // output column within tile
    const int ty = tid >> 6;        // row group
    const int ry = ty * 4;          // first of 4 consecutive rows

    // acc[p][j] holds outputs (row ry+p, couts 2j and 2j+1), init with bias
    unsigned long long acc[4][8];
    #pragma unroll
    for (int j = 0; j < 8; ++j) {
        unsigned long long bj = pack2(s_bias[2 * j], s_bias[2 * j + 1]);
        #pragma unroll
        for (int p = 0; p < 4; ++p) acc[p][j] = bj;
    }

    #pragma unroll 1
    for (int ky = 0; ky < 5; ++ky) {
        #pragma unroll
        for (int kx = 0; kx < 5; ++kx) {
            #pragma unroll
            for (int ci = 0; ci < 6; ++ci) {
                unsigned long long a2[4];
                #pragma unroll
                for (int p = 0; p < 4; ++p) {
                    float v = s_in[ci][ry + p + ky][tx + kx];
                    a2[p] = pack2(v, v);
                }
                const unsigned long long* wrow =
                    (const unsigned long long*)&s_w[(ky * 5 + kx) * 6 + ci][0];
                #pragma unroll
                for (int j = 0; j < 8; ++j) {
                    unsigned long long w = wrow[j];   // LDS.64 broadcast
                    #pragma unroll
                    for (int p = 0; p < 4; ++p) ffma2(acc[p][j], a2[p], w);
                }
            }
        }
    }

    // Store: 16 contiguous fp32 per pixel -> 4x STG.128 per pixel
    const int gx = x0 + tx;
    if (gx < WOUT) {
        #pragma unroll
        for (int p = 0; p < 4; ++p) {
            int gy = y0 + ry + p;
            if (gy < HOUT) {
                ulonglong2* op = (ulonglong2*)(out +
                    ((long long)(b * HOUT + gy) * WOUT + gx) * COUT);
                #pragma unroll
                for (int q = 0; q < 4; ++q) {
                    ulonglong2 u;
                    u.x = acc[p][2 * q];
                    u.y = acc[p][2 * q + 1];
                    op[q] = u;
                }
            }
        }
    }
}

extern "C" void kernel_launch(void* const* d_in, const int* in_sizes, int n_in,
                              void* d_out, int out_size) {
    const float* inputs = (const float*)d_in[0];
    const float* w3     = (const float*)d_in[1];
    const float* w4     = (const float*)d_in[2];
    const float* w44    = (const float*)d_in[3];
    const float* w6     = (const float*)d_in[4];
    const float* bias   = (const float*)d_in[5];

    build_weights<<<(FS * FS * CIN * COUT + 255) / 256, 256>>>(w3, w4, w44, w6);

    dim3 grid((WOUT + TW - 1) / TW, (HOUT + TH - 1) / TH, BATCHN);
    conv_dense_kernel<<<grid, 256>>>(inputs, bias, (float*)d_out);
}